// round 1
// baseline (speedup 1.0000x reference)
#include <cuda_runtime.h>

// Problem constants (fixed by the reference)
#define NB   8
#define QDIM 2048
#define KDIM 2048
#define EDIM 512

// Scratch for the energy/attention matrix: 8*2048*2048 fp32 = 134 MB.
// __device__ global (allocation-guard-safe per harness rules).
__device__ float g_energy[(size_t)NB * QDIM * KDIM];

// ---------------------------------------------------------------------------
// GEMM NT: E[b, m, n] = sum_e Q[b, m, e] * K[b, n, e]
// 128x128 tile, BK=8, 256 threads, 8x8 per-thread microtile.
// ---------------------------------------------------------------------------
__global__ __launch_bounds__(256)
void qk_kernel(const float* __restrict__ Q, const float* __restrict__ K)
{
    const int b      = blockIdx.z;
    const int tile_m = blockIdx.y * 128;   // q
    const int tile_n = blockIdx.x * 128;   // k

    const float* A = Q + (size_t)b * QDIM * EDIM;
    const float* B = K + (size_t)b * KDIM * EDIM;
    float*       C = g_energy + (size_t)b * QDIM * KDIM;

    __shared__ float As[8][128];
    __shared__ float Bs[8][128];

    const int tid   = threadIdx.x;
    const int lrow  = tid >> 1;          // 0..127
    const int lcol4 = (tid & 1) * 4;     // 0 or 4

    const int tx = tid % 16;             // n direction
    const int ty = tid / 16;             // m direction

    float acc[8][8];
    #pragma unroll
    for (int i = 0; i < 8; i++)
        #pragma unroll
        for (int j = 0; j < 8; j++) acc[i][j] = 0.0f;

    const float* aptr = A + (size_t)(tile_m + lrow) * EDIM + lcol4;
    const float* bptr = B + (size_t)(tile_n + lrow) * EDIM + lcol4;

    for (int k0 = 0; k0 < EDIM; k0 += 8) {
        float4 av = *(const float4*)(aptr + k0);
        float4 bv = *(const float4*)(bptr + k0);

        __syncthreads();
        As[lcol4 + 0][lrow] = av.x;
        As[lcol4 + 1][lrow] = av.y;
        As[lcol4 + 2][lrow] = av.z;
        As[lcol4 + 3][lrow] = av.w;
        Bs[lcol4 + 0][lrow] = bv.x;
        Bs[lcol4 + 1][lrow] = bv.y;
        Bs[lcol4 + 2][lrow] = bv.z;
        Bs[lcol4 + 3][lrow] = bv.w;
        __syncthreads();

        #pragma unroll
        for (int kk = 0; kk < 8; kk++) {
            float a_frag[8], b_frag[8];
            *(float4*)&a_frag[0] = *(const float4*)&As[kk][ty * 8];
            *(float4*)&a_frag[4] = *(const float4*)&As[kk][ty * 8 + 4];
            *(float4*)&b_frag[0] = *(const float4*)&Bs[kk][tx * 8];
            *(float4*)&b_frag[4] = *(const float4*)&Bs[kk][tx * 8 + 4];
            #pragma unroll
            for (int i = 0; i < 8; i++)
                #pragma unroll
                for (int j = 0; j < 8; j++)
                    acc[i][j] = fmaf(a_frag[i], b_frag[j], acc[i][j]);
        }
    }

    #pragma unroll
    for (int i = 0; i < 8; i++) {
        float* crow = C + (size_t)(tile_m + ty * 8 + i) * KDIM + tile_n + tx * 8;
        *(float4*)(crow)     = make_float4(acc[i][0], acc[i][1], acc[i][2], acc[i][3]);
        *(float4*)(crow + 4) = make_float4(acc[i][4], acc[i][5], acc[i][6], acc[i][7]);
    }
}

// ---------------------------------------------------------------------------
// Row softmax over g_energy: one block (256 threads) per row of 2048.
// ---------------------------------------------------------------------------
__global__ __launch_bounds__(256)
void softmax_kernel()
{
    const size_t row = blockIdx.x;                 // 0 .. NB*QDIM-1
    float* p = g_energy + row * (size_t)KDIM;
    const int tid = threadIdx.x;

    float v[8];
    float m = -3.402823466e+38f;
    #pragma unroll
    for (int i = 0; i < 8; i++) {
        v[i] = p[tid + i * 256];
        m = fmaxf(m, v[i]);
    }

    __shared__ float red[8];
    // warp-level max
    #pragma unroll
    for (int off = 16; off > 0; off >>= 1)
        m = fmaxf(m, __shfl_xor_sync(0xFFFFFFFFu, m, off));
    if ((tid & 31) == 0) red[tid >> 5] = m;
    __syncthreads();
    if (tid < 8) {
        float t = red[tid];
        #pragma unroll
        for (int off = 4; off > 0; off >>= 1)
            t = fmaxf(t, __shfl_xor_sync(0x000000FFu, t, off));
        red[tid] = t;
    }
    __syncthreads();
    m = red[0];

    float s = 0.0f;
    #pragma unroll
    for (int i = 0; i < 8; i++) {
        v[i] = __expf(v[i] - m);
        s += v[i];
    }

    __shared__ float red2[8];
    #pragma unroll
    for (int off = 16; off > 0; off >>= 1)
        s += __shfl_xor_sync(0xFFFFFFFFu, s, off);
    if ((tid & 31) == 0) red2[tid >> 5] = s;
    __syncthreads();
    if (tid < 8) {
        float t = red2[tid];
        #pragma unroll
        for (int off = 4; off > 0; off >>= 1)
            t += __shfl_xor_sync(0x000000FFu, t, off);
        red2[tid] = t;
    }
    __syncthreads();
    const float inv = 1.0f / red2[0];

    #pragma unroll
    for (int i = 0; i < 8; i++)
        p[tid + i * 256] = v[i] * inv;
}

// ---------------------------------------------------------------------------
// GEMM NN: O[b, m, e] = sum_k P[b, m, k] * V[b, k, e]
// 128x128 tile, BK=8, 256 threads, 8x8 per-thread microtile.
// ---------------------------------------------------------------------------
__global__ __launch_bounds__(256)
void pv_kernel(const float* __restrict__ V, float* __restrict__ O)
{
    const int b      = blockIdx.z;
    const int tile_m = blockIdx.y * 128;   // q
    const int tile_n = blockIdx.x * 128;   // e

    const float* A = g_energy + (size_t)b * QDIM * KDIM;
    const float* B = V + (size_t)b * KDIM * EDIM;
    float*       C = O + (size_t)b * QDIM * EDIM;

    __shared__ float As[8][128];
    __shared__ float Bs[8][128];

    const int tid   = threadIdx.x;
    const int lrow  = tid >> 1;          // 0..127   (A rows)
    const int lcol4 = (tid & 1) * 4;     // 0 or 4   (A k-offset)
    const int brow  = tid >> 5;          // 0..7     (B k-rows)
    const int bcol4 = (tid & 31) * 4;    // 0..124   (B n-cols)

    const int tx = tid % 16;             // n direction
    const int ty = tid / 16;             // m direction

    float acc[8][8];
    #pragma unroll
    for (int i = 0; i < 8; i++)
        #pragma unroll
        for (int j = 0; j < 8; j++) acc[i][j] = 0.0f;

    const float* aptr = A + (size_t)(tile_m + lrow) * KDIM + lcol4;
    const float* bptr = B + (size_t)brow * EDIM + tile_n + bcol4;

    for (int k0 = 0; k0 < KDIM; k0 += 8) {
        float4 av = *(const float4*)(aptr + k0);
        float4 bv = *(const float4*)(bptr + (size_t)k0 * EDIM);

        __syncthreads();
        As[lcol4 + 0][lrow] = av.x;
        As[lcol4 + 1][lrow] = av.y;
        As[lcol4 + 2][lrow] = av.z;
        As[lcol4 + 3][lrow] = av.w;
        *(float4*)&Bs[brow][bcol4] = bv;
        __syncthreads();

        #pragma unroll
        for (int kk = 0; kk < 8; kk++) {
            float a_frag[8], b_frag[8];
            *(float4*)&a_frag[0] = *(const float4*)&As[kk][ty * 8];
            *(float4*)&a_frag[4] = *(const float4*)&As[kk][ty * 8 + 4];
            *(float4*)&b_frag[0] = *(const float4*)&Bs[kk][tx * 8];
            *(float4*)&b_frag[4] = *(const float4*)&Bs[kk][tx * 8 + 4];
            #pragma unroll
            for (int i = 0; i < 8; i++)
                #pragma unroll
                for (int j = 0; j < 8; j++)
                    acc[i][j] = fmaf(a_frag[i], b_frag[j], acc[i][j]);
        }
    }

    #pragma unroll
    for (int i = 0; i < 8; i++) {
        float* crow = C + (size_t)(tile_m + ty * 8 + i) * EDIM + tile_n + tx * 8;
        *(float4*)(crow)     = make_float4(acc[i][0], acc[i][1], acc[i][2], acc[i][3]);
        *(float4*)(crow + 4) = make_float4(acc[i][4], acc[i][5], acc[i][6], acc[i][7]);
    }
}

// ---------------------------------------------------------------------------
extern "C" void kernel_launch(void* const* d_in, const int* in_sizes, int n_in,
                              void* d_out, int out_size)
{
    const float* Q = (const float*)d_in[0];
    const float* K = (const float*)d_in[1];
    const float* V = (const float*)d_in[2];
    float*       O = (float*)d_out;

    dim3 g1(KDIM / 128, QDIM / 128, NB);   // 16 x 16 x 8
    qk_kernel<<<g1, 256>>>(Q, K);

    softmax_kernel<<<NB * QDIM, 256>>>();

    dim3 g2(EDIM / 128, QDIM / 128, NB);   // 4 x 16 x 8
    pv_kernel<<<g2, 256>>>(V, O);
}

// round 3
// speedup vs baseline: 2.3825x; 2.3825x over previous
#include <cuda_runtime.h>
#include <cuda_fp16.h>
#include <cstdint>

#define NB   8
#define QDIM 2048
#define KDIM 2048
#define EDIM 512

typedef __half fp16;

// ---------------------------------------------------------------------------
// Device-global scratch (allocation-guard-safe)
// ---------------------------------------------------------------------------
__device__ __align__(256) fp16  g_Qh[(size_t)NB * QDIM * EDIM];
__device__ __align__(256) fp16  g_Ql[(size_t)NB * QDIM * EDIM];
__device__ __align__(256) fp16  g_Kh[(size_t)NB * KDIM * EDIM];
__device__ __align__(256) fp16  g_Kl[(size_t)NB * KDIM * EDIM];
__device__ __align__(256) fp16  g_Vth[(size_t)NB * EDIM * KDIM];  // V^T [b][e][k]
__device__ __align__(256) fp16  g_Vtl[(size_t)NB * EDIM * KDIM];
__device__ __align__(256) float g_E  [(size_t)NB * QDIM * KDIM];  // logits
__device__ __align__(256) fp16  g_Ph [(size_t)NB * QDIM * KDIM];  // softmax hi
__device__ __align__(256) fp16  g_Pl [(size_t)NB * QDIM * KDIM];  // softmax lo

// ---------------------------------------------------------------------------
// PTX helpers (all plain sm_80+ features — NO 'a'-suffix instructions)
// ---------------------------------------------------------------------------
__device__ __forceinline__ uint32_t smem_u32(const void* p) {
    uint32_t a;
    asm("{ .reg .u64 t; cvta.to.shared.u64 t, %1; cvt.u32.u64 %0, t; }" : "=r"(a) : "l"(p));
    return a;
}

#define CP_ASYNC16(dst, src) \
    asm volatile("cp.async.cg.shared.global [%0], [%1], 16;" :: "r"(dst), "l"(src))
#define CP_COMMIT() asm volatile("cp.async.commit_group;" ::: "memory")
#define CP_WAIT1()  asm volatile("cp.async.wait_group 1;" ::: "memory")
#define CP_WAIT0()  asm volatile("cp.async.wait_group 0;" ::: "memory")

#define LDSM_X4(r0, r1, r2, r3, a)                                          \
    asm volatile("ldmatrix.sync.aligned.m8n8.x4.shared.b16 {%0,%1,%2,%3}, [%4];" \
        : "=r"(r0), "=r"(r1), "=r"(r2), "=r"(r3) : "r"(a))

#define MMA16816(d, a, b0, b1)                                              \
    asm volatile("mma.sync.aligned.m16n8k16.row.col.f32.f16.f16.f32 "       \
        "{%0,%1,%2,%3},{%4,%5,%6,%7},{%8,%9},{%0,%1,%2,%3};"                \
        : "+f"((d)[0]), "+f"((d)[1]), "+f"((d)[2]), "+f"((d)[3])            \
        : "r"((a)[0]), "r"((a)[1]), "r"((a)[2]), "r"((a)[3]),               \
          "r"(b0), "r"(b1))

// ---------------------------------------------------------------------------
// Elementwise fp32 -> fp16 hi/lo split  (which: 0 = Q, 1 = K)
// ---------------------------------------------------------------------------
__global__ __launch_bounds__(256)
void split_kernel(const float* __restrict__ X, int which, int n4)
{
    fp16* Xh = which ? g_Kh : g_Qh;
    fp16* Xl = which ? g_Kl : g_Ql;
    int i = blockIdx.x * 256 + threadIdx.x;
    if (i >= n4) return;
    float4 v = ((const float4*)X)[i];
    fp16 h0 = __float2half_rn(v.x), h1 = __float2half_rn(v.y);
    fp16 h2 = __float2half_rn(v.z), h3 = __float2half_rn(v.w);
    fp16 l0 = __float2half_rn(v.x - __half2float(h0));
    fp16 l1 = __float2half_rn(v.y - __half2float(h1));
    fp16 l2 = __float2half_rn(v.z - __half2float(h2));
    fp16 l3 = __float2half_rn(v.w - __half2float(h3));
    ((__half2*)Xh)[2 * i]     = __half2(h0, h1);
    ((__half2*)Xh)[2 * i + 1] = __half2(h2, h3);
    ((__half2*)Xl)[2 * i]     = __half2(l0, l1);
    ((__half2*)Xl)[2 * i + 1] = __half2(l2, l3);
}

// ---------------------------------------------------------------------------
// V [b][k][e] fp32 -> V^T [b][e][k] fp16 hi/lo
// ---------------------------------------------------------------------------
__global__ __launch_bounds__(256)
void vtrans_kernel(const float* __restrict__ V)
{
    __shared__ float t[32][33];
    const int b  = blockIdx.z;
    const int k0 = blockIdx.x * 32;
    const int e0 = blockIdx.y * 32;
    const int tx = threadIdx.x & 31;
    const int ty = threadIdx.x >> 5;
    const float* Vb = V + (size_t)b * KDIM * EDIM;

    #pragma unroll
    for (int j = 0; j < 4; j++)
        t[ty + j * 8][tx] = Vb[(size_t)(k0 + ty + j * 8) * EDIM + e0 + tx];
    __syncthreads();

    #pragma unroll
    for (int j = 0; j < 4; j++) {
        int e = e0 + ty + j * 8;
        int k = k0 + tx;
        float x = t[tx][ty + j * 8];
        fp16 h = __float2half_rn(x);
        fp16 l = __float2half_rn(x - __half2float(h));
        size_t o = (size_t)b * EDIM * KDIM + (size_t)e * KDIM + k;
        g_Vth[o] = h;
        g_Vtl[o] = l;
    }
}

// ---------------------------------------------------------------------------
// Row softmax of g_E -> fp16 hi/lo in g_Ph/g_Pl
// ---------------------------------------------------------------------------
__global__ __launch_bounds__(256)
void softmax_split_kernel()
{
    const size_t row = blockIdx.x;
    const float* p = g_E + row * (size_t)KDIM;
    const int tid = threadIdx.x;

    float v[8];
    float m = -3.402823466e+38f;
    #pragma unroll
    for (int i = 0; i < 8; i++) { v[i] = p[tid + i * 256]; m = fmaxf(m, v[i]); }

    __shared__ float red[8];
    #pragma unroll
    for (int off = 16; off > 0; off >>= 1) m = fmaxf(m, __shfl_xor_sync(~0u, m, off));
    if ((tid & 31) == 0) red[tid >> 5] = m;
    __syncthreads();
    if (tid < 8) {
        float t = red[tid];
        #pragma unroll
        for (int off = 4; off > 0; off >>= 1) t = fmaxf(t, __shfl_xor_sync(0xFFu, t, off));
        red[tid] = t;
    }
    __syncthreads();
    m = red[0];

    float s = 0.0f;
    #pragma unroll
    for (int i = 0; i < 8; i++) { v[i] = __expf(v[i] - m); s += v[i]; }

    __shared__ float red2[8];
    #pragma unroll
    for (int off = 16; off > 0; off >>= 1) s += __shfl_xor_sync(~0u, s, off);
    if ((tid & 31) == 0) red2[tid >> 5] = s;
    __syncthreads();
    if (tid < 8) {
        float t = red2[tid];
        #pragma unroll
        for (int off = 4; off > 0; off >>= 1) t += __shfl_xor_sync(0xFFu, t, off);
        red2[tid] = t;
    }
    __syncthreads();
    const float inv = 1.0f / red2[0];

    #pragma unroll
    for (int i = 0; i < 8; i++) {
        float pv = v[i] * inv;
        fp16 h = __float2half_rn(pv);
        fp16 l = __float2half_rn(pv - __half2float(h));
        size_t o = row * (size_t)KDIM + tid + i * 256;
        g_Ph[o] = h;
        g_Pl[o] = l;
    }
}

// ---------------------------------------------------------------------------
// HMMA 3-pass split-fp16 GEMM.
//   MODE 0: E = Q . K^T   (A = Qh/Ql [2048x512],  B = Kh/Kl  [2048x512])
//   MODE 1: O = P . V     (A = Ph/Pl [2048x2048], B = Vth/Vtl [512x2048])
// CTA tile 128x128, K-chunk 64, 8 warps (2x4), warp tile 64x32.
// smem tiles: 128 rows x 64 fp16 (= 128B rows), xor-swizzled, double-buffered.
// ---------------------------------------------------------------------------
#define TILE_B  16384               // one 128x64 fp16 tile
#define STAGE_B (4 * TILE_B)        // Ah, Al, Bh, Bl
#define SMEM_T  (2 * STAGE_B)       // 131072 bytes

__device__ __forceinline__ void cp_tile(uint32_t dstbase, const fp16* src,
                                        int ld, int tid)
{
    const int c = tid & 7;                       // 16B chunk within row
    const char* s = (const char*)src + c * 16;
    const size_t row_bytes = (size_t)ld * 2;
    #pragma unroll
    for (int r0 = 0; r0 < 128; r0 += 32) {
        int r = r0 + (tid >> 3);
        uint32_t dst = dstbase + (uint32_t)r * 128u + (uint32_t)((c ^ (r & 7)) << 4);
        CP_ASYNC16(dst, s + (size_t)r * row_bytes);
    }
}

template <int MODE>
__global__ __launch_bounds__(256, 1)
void hgemm3_kernel(float* __restrict__ Oout)
{
    constexpr int LDA  = (MODE == 0) ? EDIM : KDIM;
    constexpr int LDB  = (MODE == 0) ? EDIM : KDIM;
    constexpr int LDC  = (MODE == 0) ? KDIM : EDIM;
    constexpr int KTOT = (MODE == 0) ? EDIM : KDIM;
    constexpr size_t SA = (MODE == 0) ? (size_t)QDIM * EDIM : (size_t)QDIM * KDIM;
    constexpr size_t SB = (MODE == 0) ? (size_t)KDIM * EDIM : (size_t)EDIM * KDIM;
    constexpr size_t SC = (MODE == 0) ? (size_t)QDIM * KDIM : (size_t)QDIM * EDIM;
    constexpr int NITER = KTOT / 64;

    extern __shared__ __align__(1024) uint8_t smem[];
    const uint32_t sb = smem_u32(smem);

    const int tid  = threadIdx.x;
    const int lane = tid & 31;
    const int wid  = tid >> 5;
    const int wm   = (wid >> 2) * 64;           // warp m offset in tile
    const int wn   = (wid & 3) * 32;            // warp n offset in tile
    const int b    = blockIdx.z;
    const int m0   = blockIdx.y * 128;
    const int n0   = blockIdx.x * 128;

    const fp16* Ah = ((MODE == 0) ? g_Qh : g_Ph)  + b * SA + (size_t)m0 * LDA;
    const fp16* Al = ((MODE == 0) ? g_Ql : g_Pl)  + b * SA + (size_t)m0 * LDA;
    const fp16* Bh = ((MODE == 0) ? g_Kh : g_Vth) + b * SB + (size_t)n0 * LDB;
    const fp16* Bl = ((MODE == 0) ? g_Kl : g_Vtl) + b * SB + (size_t)n0 * LDB;
    float* C = ((MODE == 0) ? g_E : Oout) + b * SC;

    float acc[4][4][4];
    #pragma unroll
    for (int i = 0; i < 4; i++)
        #pragma unroll
        for (int j = 0; j < 4; j++)
            #pragma unroll
            for (int q = 0; q < 4; q++) acc[i][j][q] = 0.0f;

    // Per-thread ldmatrix row components (fixed across iterations)
    const int a_r15 = lane & 15;      // row-within-16-group
    const int c_hi  = lane >> 4;      // 0: k-lo chunk, 1: k-hi chunk

    // Prologue: stage 0
    cp_tile(sb + 0 * TILE_B, Ah, LDA, tid);
    cp_tile(sb + 1 * TILE_B, Al, LDA, tid);
    cp_tile(sb + 2 * TILE_B, Bh, LDB, tid);
    cp_tile(sb + 3 * TILE_B, Bl, LDB, tid);
    CP_COMMIT();

    for (int it = 0; it < NITER; ++it) {
        if (it + 1 < NITER) {
            const uint32_t nb = sb + ((it + 1) & 1) * STAGE_B;
            const int k0 = (it + 1) * 64;
            cp_tile(nb + 0 * TILE_B, Ah + k0, LDA, tid);
            cp_tile(nb + 1 * TILE_B, Al + k0, LDA, tid);
            cp_tile(nb + 2 * TILE_B, Bh + k0, LDB, tid);
            cp_tile(nb + 3 * TILE_B, Bl + k0, LDB, tid);
            CP_COMMIT();
            CP_WAIT1();
        } else {
            CP_WAIT0();
        }
        __syncthreads();

        const uint32_t SBASE = sb + (it & 1) * STAGE_B;

        #pragma unroll
        for (int combo = 0; combo < 3; ++combo) {
            const uint32_t Ab = SBASE + ((combo == 2) ? TILE_B : 0);
            const uint32_t Bb = SBASE + 2 * TILE_B + ((combo == 1) ? TILE_B : 0);

            #pragma unroll
            for (int kk = 0; kk < 4; ++kk) {
                uint32_t a[4][4];
                #pragma unroll
                for (int mi = 0; mi < 4; ++mi) {
                    const int row = wm + mi * 16 + a_r15;
                    const uint32_t addr = Ab + (uint32_t)row * 128u
                        + (uint32_t)(((kk * 2 + c_hi) ^ (row & 7)) << 4);
                    LDSM_X4(a[mi][0], a[mi][1], a[mi][2], a[mi][3], addr);
                }
                uint32_t bq[2][4];
                #pragma unroll
                for (int nj = 0; nj < 2; ++nj) {
                    const int row = wn + nj * 16 + a_r15;
                    const uint32_t addr = Bb + (uint32_t)row * 128u
                        + (uint32_t)(((kk * 2 + c_hi) ^ (row & 7)) << 4);
                    LDSM_X4(bq[nj][0], bq[nj][1], bq[nj][2], bq[nj][3], addr);
                }
                #pragma unroll
                for (int mi = 0; mi < 4; ++mi) {
                    #pragma unroll
                    for (int ni = 0; ni < 4; ++ni) {
                        const uint32_t b0 = bq[ni >> 1][(ni & 1) ? 1 : 0];
                        const uint32_t b1 = bq[ni >> 1][(ni & 1) ? 3 : 2];
                        MMA16816(acc[mi][ni], a[mi], b0, b1);
                    }
                }
            }
        }
        __syncthreads();
    }

    // Epilogue: fragment layout c0,c1 -> (row g, col 2ti..); c2,c3 -> row g+8
    const int g  = lane >> 2;
    const int ti = lane & 3;
    #pragma unroll
    for (int mi = 0; mi < 4; ++mi) {
        #pragma unroll
        for (int ni = 0; ni < 4; ++ni) {
            const int row = m0 + wm + mi * 16 + g;
            const int col = n0 + wn + ni * 8 + ti * 2;
            *(float2*)&C[(size_t)row * LDC + col] =
                make_float2(acc[mi][ni][0], acc[mi][ni][1]);
            *(float2*)&C[(size_t)(row + 8) * LDC + col] =
                make_float2(acc[mi][ni][2], acc[mi][ni][3]);
        }
    }
}

// ---------------------------------------------------------------------------
extern "C" void kernel_launch(void* const* d_in, const int* in_sizes, int n_in,
                              void* d_out, int out_size)
{
    const float* Q = (const float*)d_in[0];
    const float* K = (const float*)d_in[1];
    const float* V = (const float*)d_in[2];
    float*       O = (float*)d_out;

    cudaFuncSetAttribute(hgemm3_kernel<0>, cudaFuncAttributeMaxDynamicSharedMemorySize, SMEM_T);
    cudaFuncSetAttribute(hgemm3_kernel<1>, cudaFuncAttributeMaxDynamicSharedMemorySize, SMEM_T);

    const int n4 = NB * QDIM * EDIM / 4;
    split_kernel<<<(n4 + 255) / 256, 256>>>(Q, 0, n4);
    split_kernel<<<(n4 + 255) / 256, 256>>>(K, 1, n4);
    vtrans_kernel<<<dim3(KDIM / 32, EDIM / 32, NB), 256>>>(V);

    hgemm3_kernel<0><<<dim3(KDIM / 128, QDIM / 128, NB), 256, SMEM_T>>>(nullptr);

    softmax_split_kernel<<<NB * QDIM, 256>>>();

    hgemm3_kernel<1><<<dim3(EDIM / 128, QDIM / 128, NB), 256, SMEM_T>>>(O);
}

// round 5
// speedup vs baseline: 2.4284x; 1.0193x over previous
#include <cuda_runtime.h>
#include <cuda_fp16.h>
#include <cstdint>

#define NB   8
#define QDIM 2048
#define KDIM 2048
#define EDIM 512

typedef __half fp16;

// ---------------------------------------------------------------------------
// Device-global scratch (allocation-guard-safe)
// ---------------------------------------------------------------------------
__device__ __align__(256) fp16  g_Qh[(size_t)NB * QDIM * EDIM];
__device__ __align__(256) fp16  g_Ql[(size_t)NB * QDIM * EDIM];
__device__ __align__(256) fp16  g_Kh[(size_t)NB * KDIM * EDIM];
__device__ __align__(256) fp16  g_Kl[(size_t)NB * KDIM * EDIM];
__device__ __align__(256) fp16  g_Vth[(size_t)NB * EDIM * KDIM];  // V^T [b][e][k]
__device__ __align__(256) fp16  g_Vtl[(size_t)NB * EDIM * KDIM];
__device__ __align__(256) float g_E  [(size_t)NB * QDIM * KDIM];  // logits
__device__ __align__(256) fp16  g_Ph [(size_t)NB * QDIM * KDIM];  // softmax hi
__device__ __align__(256) fp16  g_Pl [(size_t)NB * QDIM * KDIM];  // softmax lo

// ---------------------------------------------------------------------------
// PTX helpers (plain sm_80+ features only — virtual arch is compute_103)
// ---------------------------------------------------------------------------
__device__ __forceinline__ uint32_t smem_u32(const void* p) {
    uint32_t a;
    asm("{ .reg .u64 t; cvta.to.shared.u64 t, %1; cvt.u32.u64 %0, t; }" : "=r"(a) : "l"(p));
    return a;
}

__device__ __forceinline__ uint32_t h2_u32(__half2 h) {
    union { __half2 h; uint32_t u; } c;
    c.h = h;
    return c.u;
}

#define CP_ASYNC16(dst, src) \
    asm volatile("cp.async.cg.shared.global [%0], [%1], 16;" :: "r"(dst), "l"(src))
#define CP_COMMIT() asm volatile("cp.async.commit_group;" ::: "memory")
#define CP_WAIT1()  asm volatile("cp.async.wait_group 1;" ::: "memory")
#define CP_WAIT0()  asm volatile("cp.async.wait_group 0;" ::: "memory")

#define LDSM_X4(r0, r1, r2, r3, a)                                          \
    asm volatile("ldmatrix.sync.aligned.m8n8.x4.shared.b16 {%0,%1,%2,%3}, [%4];" \
        : "=r"(r0), "=r"(r1), "=r"(r2), "=r"(r3) : "r"(a))

#define MMA16816(d, a, b0, b1)                                              \
    asm volatile("mma.sync.aligned.m16n8k16.row.col.f32.f16.f16.f32 "       \
        "{%0,%1,%2,%3},{%4,%5,%6,%7},{%8,%9},{%0,%1,%2,%3};"                \
        : "+f"((d)[0]), "+f"((d)[1]), "+f"((d)[2]), "+f"((d)[3])            \
        : "r"((a)[0]), "r"((a)[1]), "r"((a)[2]), "r"((a)[3]),               \
          "r"(b0), "r"(b1))

// ---------------------------------------------------------------------------
// Elementwise fp32 -> fp16 hi/lo split  (which: 0 = Q, 1 = K)
// ---------------------------------------------------------------------------
__global__ __launch_bounds__(256)
void split_kernel(const float* __restrict__ X, int which, int n4)
{
    fp16* Xh = which ? g_Kh : g_Qh;
    fp16* Xl = which ? g_Kl : g_Ql;
    int i = blockIdx.x * 256 + threadIdx.x;
    if (i >= n4) return;
    float4 v = ((const float4*)X)[i];
    fp16 h0 = __float2half_rn(v.x), h1 = __float2half_rn(v.y);
    fp16 h2 = __float2half_rn(v.z), h3 = __float2half_rn(v.w);
    fp16 l0 = __float2half_rn(v.x - __half2float(h0));
    fp16 l1 = __float2half_rn(v.y - __half2float(h1));
    fp16 l2 = __float2half_rn(v.z - __half2float(h2));
    fp16 l3 = __float2half_rn(v.w - __half2float(h3));
    ((__half2*)Xh)[2 * i]     = __half2(h0, h1);
    ((__half2*)Xh)[2 * i + 1] = __half2(h2, h3);
    ((__half2*)Xl)[2 * i]     = __half2(l0, l1);
    ((__half2*)Xl)[2 * i + 1] = __half2(l2, l3);
}

// ---------------------------------------------------------------------------
// V [b][k][e] fp32 -> V^T [b][e][k] fp16 hi/lo
// ---------------------------------------------------------------------------
__global__ __launch_bounds__(256)
void vtrans_kernel(const float* __restrict__ V)
{
    __shared__ float t[32][33];
    const int b  = blockIdx.z;
    const int k0 = blockIdx.x * 32;
    const int e0 = blockIdx.y * 32;
    const int tx = threadIdx.x & 31;
    const int ty = threadIdx.x >> 5;
    const float* Vb = V + (size_t)b * KDIM * EDIM;

    #pragma unroll
    for (int j = 0; j < 4; j++)
        t[ty + j * 8][tx] = Vb[(size_t)(k0 + ty + j * 8) * EDIM + e0 + tx];
    __syncthreads();

    #pragma unroll
    for (int j = 0; j < 4; j++) {
        int e = e0 + ty + j * 8;
        int k = k0 + tx;
        float x = t[tx][ty + j * 8];
        fp16 h = __float2half_rn(x);
        fp16 l = __float2half_rn(x - __half2float(h));
        size_t o = (size_t)b * EDIM * KDIM + (size_t)e * KDIM + k;
        g_Vth[o] = h;
        g_Vtl[o] = l;
    }
}

// ---------------------------------------------------------------------------
// Row softmax of g_E -> fp16 hi/lo in g_Ph/g_Pl  (float4 I/O)
// ---------------------------------------------------------------------------
__global__ __launch_bounds__(256)
void softmax_split_kernel()
{
    const size_t row = blockIdx.x;
    const float* p = g_E + row * (size_t)KDIM;
    const int tid = threadIdx.x;

    float4 va = ((const float4*)p)[tid];
    float4 vb = ((const float4*)p)[tid + 256];

    float m = fmaxf(fmaxf(fmaxf(va.x, va.y), fmaxf(va.z, va.w)),
                    fmaxf(fmaxf(vb.x, vb.y), fmaxf(vb.z, vb.w)));

    __shared__ float red[8];
    #pragma unroll
    for (int off = 16; off > 0; off >>= 1) m = fmaxf(m, __shfl_xor_sync(~0u, m, off));
    if ((tid & 31) == 0) red[tid >> 5] = m;
    __syncthreads();
    if (tid < 8) {
        float t = red[tid];
        #pragma unroll
        for (int off = 4; off > 0; off >>= 1) t = fmaxf(t, __shfl_xor_sync(0xFFu, t, off));
        red[tid] = t;
    }
    __syncthreads();
    m = red[0];

    va.x = __expf(va.x - m); va.y = __expf(va.y - m);
    va.z = __expf(va.z - m); va.w = __expf(va.w - m);
    vb.x = __expf(vb.x - m); vb.y = __expf(vb.y - m);
    vb.z = __expf(vb.z - m); vb.w = __expf(vb.w - m);
    float s = (va.x + va.y) + (va.z + va.w) + (vb.x + vb.y) + (vb.z + vb.w);

    __shared__ float red2[8];
    #pragma unroll
    for (int off = 16; off > 0; off >>= 1) s += __shfl_xor_sync(~0u, s, off);
    if ((tid & 31) == 0) red2[tid >> 5] = s;
    __syncthreads();
    if (tid < 8) {
        float t = red2[tid];
        #pragma unroll
        for (int off = 4; off > 0; off >>= 1) t += __shfl_xor_sync(0xFFu, t, off);
        red2[tid] = t;
    }
    __syncthreads();
    const float inv = 1.0f / red2[0];

    fp16* ph = g_Ph + row * (size_t)KDIM;
    fp16* pl = g_Pl + row * (size_t)KDIM;
    float q[8] = {va.x * inv, va.y * inv, va.z * inv, va.w * inv,
                  vb.x * inv, vb.y * inv, vb.z * inv, vb.w * inv};
    __half2 hh[4], ll[4];
    #pragma unroll
    for (int j = 0; j < 4; j++) {
        fp16 h0 = __float2half_rn(q[j * 2]);
        fp16 h1 = __float2half_rn(q[j * 2 + 1]);
        hh[j] = __half2(h0, h1);
        ll[j] = __half2(__float2half_rn(q[j * 2]     - __half2float(h0)),
                        __float2half_rn(q[j * 2 + 1] - __half2float(h1)));
    }
    // q[0..3] correspond to cols tid*4.., q[4..7] to cols 1024 + tid*4..
    *(uint2*)&ph[tid * 4]        = make_uint2(h2_u32(hh[0]), h2_u32(hh[1]));
    *(uint2*)&ph[1024 + tid * 4] = make_uint2(h2_u32(hh[2]), h2_u32(hh[3]));
    *(uint2*)&pl[tid * 4]        = make_uint2(h2_u32(ll[0]), h2_u32(ll[1]));
    *(uint2*)&pl[1024 + tid * 4] = make_uint2(h2_u32(ll[2]), h2_u32(ll[3]));
}

// ---------------------------------------------------------------------------
// HMMA 3-pass split-fp16 GEMM.
//   MODE 0: E = Q . K^T   (A = Qh/Ql [2048x512],  B = Kh/Kl  [2048x512])
//   MODE 1: O = P . V     (A = Ph/Pl [2048x2048], B = Vth/Vtl [512x2048])
// CTA tile 128x128, K-chunk 64, 8 warps (2x4), warp tile 64x32.
// 3-stage cp.async ring; fragment double-buffering across 12 MMA steps/chunk.
// ---------------------------------------------------------------------------
#define TILE_B  16384               // one 128x64 fp16 tile
#define STAGE_B (4 * TILE_B)        // Ah, Al, Bh, Bl
#define SMEM_T  (3 * STAGE_B)       // 196608 bytes

__device__ __forceinline__ void cp_tile(uint32_t dstbase, const fp16* src,
                                        int ld, int tid)
{
    const int c = tid & 7;                       // 16B chunk within row
    const char* s = (const char*)src + c * 16;
    const size_t row_bytes = (size_t)ld * 2;
    #pragma unroll
    for (int r0 = 0; r0 < 128; r0 += 32) {
        int r = r0 + (tid >> 3);
        uint32_t dst = dstbase + (uint32_t)r * 128u + (uint32_t)((c ^ (r & 7)) << 4);
        CP_ASYNC16(dst, s + (size_t)r * row_bytes);
    }
}

// Load all fragments for step s (combo = s>>2, kk = s&3).
__device__ __forceinline__ void load_step(uint32_t SBASE, int s,
                                          int wm, int wn, int a_r15, int c_hi,
                                          uint32_t af[4][4], uint32_t bf[2][4])
{
    const int combo = s >> 2;
    const int kk    = s & 3;
    const uint32_t Ab = SBASE + ((combo == 2) ? TILE_B : 0);
    const uint32_t Bb = SBASE + 2 * TILE_B + ((combo == 1) ? TILE_B : 0);
    #pragma unroll
    for (int mi = 0; mi < 4; ++mi) {
        const int row = wm + mi * 16 + a_r15;
        const uint32_t addr = Ab + (uint32_t)row * 128u
            + (uint32_t)(((kk * 2 + c_hi) ^ (row & 7)) << 4);
        LDSM_X4(af[mi][0], af[mi][1], af[mi][2], af[mi][3], addr);
    }
    #pragma unroll
    for (int nj = 0; nj < 2; ++nj) {
        const int row = wn + nj * 16 + a_r15;
        const uint32_t addr = Bb + (uint32_t)row * 128u
            + (uint32_t)(((kk * 2 + c_hi) ^ (row & 7)) << 4);
        LDSM_X4(bf[nj][0], bf[nj][1], bf[nj][2], bf[nj][3], addr);
    }
}

__device__ __forceinline__ void mma_step(float acc[4][4][4],
                                         uint32_t af[4][4], uint32_t bf[2][4])
{
    #pragma unroll
    for (int mi = 0; mi < 4; ++mi) {
        #pragma unroll
        for (int ni = 0; ni < 4; ++ni) {
            const uint32_t b0 = bf[ni >> 1][(ni & 1) ? 1 : 0];
            const uint32_t b1 = bf[ni >> 1][(ni & 1) ? 3 : 2];
            MMA16816(acc[mi][ni], af[mi], b0, b1);
        }
    }
}

template <int MODE>
__global__ __launch_bounds__(256, 1)
void hgemm3_kernel(float* __restrict__ Oout)
{
    constexpr int LDA  = (MODE == 0) ? EDIM : KDIM;
    constexpr int LDB  = (MODE == 0) ? EDIM : KDIM;
    constexpr int LDC  = (MODE == 0) ? KDIM : EDIM;
    constexpr int KTOT = (MODE == 0) ? EDIM : KDIM;
    constexpr size_t SA = (MODE == 0) ? (size_t)QDIM * EDIM : (size_t)QDIM * KDIM;
    constexpr size_t SB = (MODE == 0) ? (size_t)KDIM * EDIM : (size_t)EDIM * KDIM;
    constexpr size_t SC = (MODE == 0) ? (size_t)QDIM * KDIM : (size_t)QDIM * EDIM;
    constexpr int NITER = KTOT / 64;

    extern __shared__ __align__(1024) uint8_t smem[];
    const uint32_t sb = smem_u32(smem);

    const int tid  = threadIdx.x;
    const int lane = tid & 31;
    const int wid  = tid >> 5;
    const int wm   = (wid >> 2) * 64;
    const int wn   = (wid & 3) * 32;
    const int b    = blockIdx.z;
    const int m0   = blockIdx.y * 128;
    const int n0   = blockIdx.x * 128;

    const fp16* Ah = ((MODE == 0) ? g_Qh : g_Ph)  + b * SA + (size_t)m0 * LDA;
    const fp16* Al = ((MODE == 0) ? g_Ql : g_Pl)  + b * SA + (size_t)m0 * LDA;
    const fp16* Bh = ((MODE == 0) ? g_Kh : g_Vth) + b * SB + (size_t)n0 * LDB;
    const fp16* Bl = ((MODE == 0) ? g_Kl : g_Vtl) + b * SB + (size_t)n0 * LDB;
    float* C = ((MODE == 0) ? g_E : Oout) + b * SC;

    float acc[4][4][4];
    #pragma unroll
    for (int i = 0; i < 4; i++)
        #pragma unroll
        for (int j = 0; j < 4; j++)
            #pragma unroll
            for (int q = 0; q < 4; q++) acc[i][j][q] = 0.0f;

    const int a_r15 = lane & 15;
    const int c_hi  = lane >> 4;

    // Prologue: fill ring stages 0 and 1
    cp_tile(sb + 0 * TILE_B, Ah, LDA, tid);
    cp_tile(sb + 1 * TILE_B, Al, LDA, tid);
    cp_tile(sb + 2 * TILE_B, Bh, LDB, tid);
    cp_tile(sb + 3 * TILE_B, Bl, LDB, tid);
    CP_COMMIT();
    {
        const uint32_t nb = sb + STAGE_B;
        cp_tile(nb + 0 * TILE_B, Ah + 64, LDA, tid);
        cp_tile(nb + 1 * TILE_B, Al + 64, LDA, tid);
        cp_tile(nb + 2 * TILE_B, Bh + 64, LDB, tid);
        cp_tile(nb + 3 * TILE_B, Bl + 64, LDB, tid);
        CP_COMMIT();
    }

    for (int it = 0; it < NITER; ++it) {
        if (it + 1 < NITER) CP_WAIT1(); else CP_WAIT0();
        __syncthreads();

        if (it + 2 < NITER) {
            const uint32_t nb = sb + ((it + 2) % 3) * STAGE_B;
            const int k0 = (it + 2) * 64;
            cp_tile(nb + 0 * TILE_B, Ah + k0, LDA, tid);
            cp_tile(nb + 1 * TILE_B, Al + k0, LDA, tid);
            cp_tile(nb + 2 * TILE_B, Bh + k0, LDB, tid);
            cp_tile(nb + 3 * TILE_B, Bl + k0, LDB, tid);
            CP_COMMIT();
        }

        const uint32_t SBASE = sb + (it % 3) * STAGE_B;

        uint32_t af[2][4][4], bf[2][2][4];
        load_step(SBASE, 0, wm, wn, a_r15, c_hi, af[0], bf[0]);
        #pragma unroll
        for (int s = 0; s < 12; ++s) {
            if (s + 1 < 12)
                load_step(SBASE, s + 1, wm, wn, a_r15, c_hi,
                          af[(s + 1) & 1], bf[(s + 1) & 1]);
            mma_step(acc, af[s & 1], bf[s & 1]);
        }
    }

    // Epilogue
    const int g  = lane >> 2;
    const int ti = lane & 3;
    #pragma unroll
    for (int mi = 0; mi < 4; ++mi) {
        #pragma unroll
        for (int ni = 0; ni < 4; ++ni) {
            const int row = m0 + wm + mi * 16 + g;
            const int col = n0 + wn + ni * 8 + ti * 2;
            *(float2*)&C[(size_t)row * LDC + col] =
                make_float2(acc[mi][ni][0], acc[mi][ni][1]);
            *(float2*)&C[(size_t)(row + 8) * LDC + col] =
                make_float2(acc[mi][ni][2], acc[mi][ni][3]);
        }
    }
}

// ---------------------------------------------------------------------------
extern "C" void kernel_launch(void* const* d_in, const int* in_sizes, int n_in,
                              void* d_out, int out_size)
{
    const float* Q = (const float*)d_in[0];
    const float* K = (const float*)d_in[1];
    const float* V = (const float*)d_in[2];
    float*       O = (float*)d_out;

    cudaFuncSetAttribute(hgemm3_kernel<0>, cudaFuncAttributeMaxDynamicSharedMemorySize, SMEM_T);
    cudaFuncSetAttribute(hgemm3_kernel<1>, cudaFuncAttributeMaxDynamicSharedMemorySize, SMEM_T);

    const int n4 = NB * QDIM * EDIM / 4;
    split_kernel<<<(n4 + 255) / 256, 256>>>(Q, 0, n4);
    split_kernel<<<(n4 + 255) / 256, 256>>>(K, 1, n4);
    vtrans_kernel<<<dim3(KDIM / 32, EDIM / 32, NB), 256>>>(V);

    hgemm3_kernel<0><<<dim3(KDIM / 128, QDIM / 128, NB), 256, SMEM_T>>>(nullptr);

    softmax_split_kernel<<<NB * QDIM, 256>>>();

    hgemm3_kernel<1><<<dim3(EDIM / 128, QDIM / 128, NB), 256, SMEM_T>>>(O);
}

// round 6
// speedup vs baseline: 2.6584x; 1.0947x over previous
#include <cuda_runtime.h>
#include <cuda_fp16.h>
#include <cstdint>

#define NB   8
#define QDIM 2048
#define KDIM 2048
#define EDIM 512

typedef __half fp16;

// ---------------------------------------------------------------------------
// Device-global scratch (allocation-guard-safe)
// ---------------------------------------------------------------------------
__device__ __align__(256) fp16  g_Qh[(size_t)NB * QDIM * EDIM];
__device__ __align__(256) fp16  g_Ql[(size_t)NB * QDIM * EDIM];
__device__ __align__(256) fp16  g_Kh[(size_t)NB * KDIM * EDIM];
__device__ __align__(256) fp16  g_Kl[(size_t)NB * KDIM * EDIM];
__device__ __align__(256) fp16  g_Vth[(size_t)NB * EDIM * KDIM];  // V^T [b][e][k]
__device__ __align__(256) fp16  g_Vtl[(size_t)NB * EDIM * KDIM];
__device__ __align__(256) float g_E  [(size_t)NB * QDIM * KDIM];  // logits
__device__ __align__(256) fp16  g_Ph [(size_t)NB * QDIM * KDIM];  // softmax hi
__device__ __align__(256) fp16  g_Pl [(size_t)NB * QDIM * KDIM];  // softmax lo

// ---------------------------------------------------------------------------
// PTX helpers (plain sm_80+ features only — virtual arch is compute_103)
// ---------------------------------------------------------------------------
__device__ __forceinline__ uint32_t smem_u32(const void* p) {
    uint32_t a;
    asm("{ .reg .u64 t; cvta.to.shared.u64 t, %1; cvt.u32.u64 %0, t; }" : "=r"(a) : "l"(p));
    return a;
}

__device__ __forceinline__ uint32_t h2_u32(__half2 h) {
    union { __half2 h; uint32_t u; } c;
    c.h = h;
    return c.u;
}

#define CP_ASYNC16(dst, src) \
    asm volatile("cp.async.cg.shared.global [%0], [%1], 16;" :: "r"(dst), "l"(src))
#define CP_COMMIT() asm volatile("cp.async.commit_group;" ::: "memory")
#define CP_WAIT0()  asm volatile("cp.async.wait_group 0;" ::: "memory")

#define LDSM_X4(r0, r1, r2, r3, a)                                          \
    asm volatile("ldmatrix.sync.aligned.m8n8.x4.shared.b16 {%0,%1,%2,%3}, [%4];" \
        : "=r"(r0), "=r"(r1), "=r"(r2), "=r"(r3) : "r"(a))

#define MMA16816(d, a, b0, b1)                                              \
    asm volatile("mma.sync.aligned.m16n8k16.row.col.f32.f16.f16.f32 "       \
        "{%0,%1,%2,%3},{%4,%5,%6,%7},{%8,%9},{%0,%1,%2,%3};"                \
        : "+f"((d)[0]), "+f"((d)[1]), "+f"((d)[2]), "+f"((d)[3])            \
        : "r"((a)[0]), "r"((a)[1]), "r"((a)[2]), "r"((a)[3]),               \
          "r"(b0), "r"(b1))

// ---------------------------------------------------------------------------
// Elementwise fp32 -> fp16 hi/lo split  (which: 0 = Q, 1 = K)
// ---------------------------------------------------------------------------
__global__ __launch_bounds__(256)
void split_kernel(const float* __restrict__ X, int which, int n4)
{
    fp16* Xh = which ? g_Kh : g_Qh;
    fp16* Xl = which ? g_Kl : g_Ql;
    int i = blockIdx.x * 256 + threadIdx.x;
    if (i >= n4) return;
    float4 v = ((const float4*)X)[i];
    fp16 h0 = __float2half_rn(v.x), h1 = __float2half_rn(v.y);
    fp16 h2 = __float2half_rn(v.z), h3 = __float2half_rn(v.w);
    fp16 l0 = __float2half_rn(v.x - __half2float(h0));
    fp16 l1 = __float2half_rn(v.y - __half2float(h1));
    fp16 l2 = __float2half_rn(v.z - __half2float(h2));
    fp16 l3 = __float2half_rn(v.w - __half2float(h3));
    ((__half2*)Xh)[2 * i]     = __half2(h0, h1);
    ((__half2*)Xh)[2 * i + 1] = __half2(h2, h3);
    ((__half2*)Xl)[2 * i]     = __half2(l0, l1);
    ((__half2*)Xl)[2 * i + 1] = __half2(l2, l3);
}

// ---------------------------------------------------------------------------
// V [b][k][e] fp32 -> V^T [b][e][k] fp16 hi/lo
// ---------------------------------------------------------------------------
__global__ __launch_bounds__(256)
void vtrans_kernel(const float* __restrict__ V)
{
    __shared__ float t[32][33];
    const int b  = blockIdx.z;
    const int k0 = blockIdx.x * 32;
    const int e0 = blockIdx.y * 32;
    const int tx = threadIdx.x & 31;
    const int ty = threadIdx.x >> 5;
    const float* Vb = V + (size_t)b * KDIM * EDIM;

    #pragma unroll
    for (int j = 0; j < 4; j++)
        t[ty + j * 8][tx] = Vb[(size_t)(k0 + ty + j * 8) * EDIM + e0 + tx];
    __syncthreads();

    #pragma unroll
    for (int j = 0; j < 4; j++) {
        int e = e0 + ty + j * 8;
        int k = k0 + tx;
        float x = t[tx][ty + j * 8];
        fp16 h = __float2half_rn(x);
        fp16 l = __float2half_rn(x - __half2float(h));
        size_t o = (size_t)b * EDIM * KDIM + (size_t)e * KDIM + k;
        g_Vth[o] = h;
        g_Vtl[o] = l;
    }
}

// ---------------------------------------------------------------------------
// Row softmax of g_E -> fp16 hi/lo in g_Ph/g_Pl  (float4 I/O)
// ---------------------------------------------------------------------------
__global__ __launch_bounds__(256)
void softmax_split_kernel()
{
    const size_t row = blockIdx.x;
    const float* p = g_E + row * (size_t)KDIM;
    const int tid = threadIdx.x;

    float4 va = ((const float4*)p)[tid];
    float4 vb = ((const float4*)p)[tid + 256];

    float m = fmaxf(fmaxf(fmaxf(va.x, va.y), fmaxf(va.z, va.w)),
                    fmaxf(fmaxf(vb.x, vb.y), fmaxf(vb.z, vb.w)));

    __shared__ float red[8];
    #pragma unroll
    for (int off = 16; off > 0; off >>= 1) m = fmaxf(m, __shfl_xor_sync(~0u, m, off));
    if ((tid & 31) == 0) red[tid >> 5] = m;
    __syncthreads();
    if (tid < 8) {
        float t = red[tid];
        #pragma unroll
        for (int off = 4; off > 0; off >>= 1) t = fmaxf(t, __shfl_xor_sync(0xFFu, t, off));
        red[tid] = t;
    }
    __syncthreads();
    m = red[0];

    va.x = __expf(va.x - m); va.y = __expf(va.y - m);
    va.z = __expf(va.z - m); va.w = __expf(va.w - m);
    vb.x = __expf(vb.x - m); vb.y = __expf(vb.y - m);
    vb.z = __expf(vb.z - m); vb.w = __expf(vb.w - m);
    float s = (va.x + va.y) + (va.z + va.w) + (vb.x + vb.y) + (vb.z + vb.w);

    __shared__ float red2[8];
    #pragma unroll
    for (int off = 16; off > 0; off >>= 1) s += __shfl_xor_sync(~0u, s, off);
    if ((tid & 31) == 0) red2[tid >> 5] = s;
    __syncthreads();
    if (tid < 8) {
        float t = red2[tid];
        #pragma unroll
        for (int off = 4; off > 0; off >>= 1) t += __shfl_xor_sync(0xFFu, t, off);
        red2[tid] = t;
    }
    __syncthreads();
    const float inv = 1.0f / red2[0];

    fp16* ph = g_Ph + row * (size_t)KDIM;
    fp16* pl = g_Pl + row * (size_t)KDIM;
    float q[8] = {va.x * inv, va.y * inv, va.z * inv, va.w * inv,
                  vb.x * inv, vb.y * inv, vb.z * inv, vb.w * inv};
    __half2 hh[4], ll[4];
    #pragma unroll
    for (int j = 0; j < 4; j++) {
        fp16 h0 = __float2half_rn(q[j * 2]);
        fp16 h1 = __float2half_rn(q[j * 2 + 1]);
        hh[j] = __half2(h0, h1);
        ll[j] = __half2(__float2half_rn(q[j * 2]     - __half2float(h0)),
                        __float2half_rn(q[j * 2 + 1] - __half2float(h1)));
    }
    *(uint2*)&ph[tid * 4]        = make_uint2(h2_u32(hh[0]), h2_u32(hh[1]));
    *(uint2*)&ph[1024 + tid * 4] = make_uint2(h2_u32(hh[2]), h2_u32(hh[3]));
    *(uint2*)&pl[tid * 4]        = make_uint2(h2_u32(ll[0]), h2_u32(ll[1]));
    *(uint2*)&pl[1024 + tid * 4] = make_uint2(h2_u32(ll[2]), h2_u32(ll[3]));
}

// ---------------------------------------------------------------------------
// HMMA 3-pass split-fp16 GEMM.
//   MODE 0: E = Q . K^T   (A = Qh/Ql [2048x512],  B = Kh/Kl  [2048x512])
//   MODE 1: O = P . V     (A = Ph/Pl [2048x2048], B = Vth/Vtl [512x2048])
// CTA tile 128x256, 512 threads (16 warps, 2x8 grid), warp tile 64x32.
// K-chunk 64, 2-stage cp.async ring, kk-major pass order w/ fragment reuse.
// ---------------------------------------------------------------------------
#define TILE_A_B 16384              // 128 rows x 128B  (A hi or lo)
#define TILE_B_B 32768              // 256 rows x 128B  (B hi or lo)
#define OFF_AH   0
#define OFF_AL   16384
#define OFF_BH   32768
#define OFF_BL   65536
#define STAGE_B  98304
#define SMEM_T   (2 * STAGE_B)      // 196608 bytes

// Copy a ROWS x 64 fp16 tile (row-major, stride ld halfs) into swizzled smem.
template <int ROWS>
__device__ __forceinline__ void cp_tile(uint32_t dstbase, const fp16* src,
                                        int ld, int tid)
{
    const int c = tid & 7;                       // 16B chunk within 128B row
    const char* s = (const char*)src + c * 16;
    const size_t row_bytes = (size_t)ld * 2;
    #pragma unroll
    for (int r0 = 0; r0 < ROWS; r0 += 64) {
        int r = r0 + (tid >> 3);                 // 512 threads -> 64 rows/step
        uint32_t dst = dstbase + (uint32_t)r * 128u + (uint32_t)((c ^ (r & 7)) << 4);
        CP_ASYNC16(dst, s + (size_t)r * row_bytes);
    }
}

__device__ __forceinline__ void lds_a(uint32_t base, int kk, int wm,
                                      int a_r15, int c_hi, uint32_t af[4][4])
{
    #pragma unroll
    for (int mi = 0; mi < 4; ++mi) {
        const int row = wm + mi * 16 + a_r15;
        const uint32_t addr = base + (uint32_t)row * 128u
            + (uint32_t)(((kk * 2 + c_hi) ^ (row & 7)) << 4);
        LDSM_X4(af[mi][0], af[mi][1], af[mi][2], af[mi][3], addr);
    }
}

__device__ __forceinline__ void lds_b(uint32_t base, int kk, int wn,
                                      int a_r15, int c_hi, uint32_t bf[2][4])
{
    #pragma unroll
    for (int nj = 0; nj < 2; ++nj) {
        const int row = wn + nj * 16 + a_r15;
        const uint32_t addr = base + (uint32_t)row * 128u
            + (uint32_t)(((kk * 2 + c_hi) ^ (row & 7)) << 4);
        LDSM_X4(bf[nj][0], bf[nj][1], bf[nj][2], bf[nj][3], addr);
    }
}

__device__ __forceinline__ void mma_step(float acc[4][4][4],
                                         uint32_t af[4][4], uint32_t bf[2][4])
{
    #pragma unroll
    for (int mi = 0; mi < 4; ++mi) {
        #pragma unroll
        for (int ni = 0; ni < 4; ++ni) {
            const uint32_t b0 = bf[ni >> 1][(ni & 1) ? 1 : 0];
            const uint32_t b1 = bf[ni >> 1][(ni & 1) ? 3 : 2];
            MMA16816(acc[mi][ni], af[mi], b0, b1);
        }
    }
}

template <int MODE>
__global__ __launch_bounds__(512, 1)
void hgemm3_kernel(float* __restrict__ Oout)
{
    constexpr int LDA  = (MODE == 0) ? EDIM : KDIM;
    constexpr int LDB  = (MODE == 0) ? EDIM : KDIM;
    constexpr int LDC  = (MODE == 0) ? KDIM : EDIM;
    constexpr int KTOT = (MODE == 0) ? EDIM : KDIM;
    constexpr size_t SA = (MODE == 0) ? (size_t)QDIM * EDIM : (size_t)QDIM * KDIM;
    constexpr size_t SB = (MODE == 0) ? (size_t)KDIM * EDIM : (size_t)EDIM * KDIM;
    constexpr size_t SC = (MODE == 0) ? (size_t)QDIM * KDIM : (size_t)QDIM * EDIM;
    constexpr int NITER = KTOT / 64;

    extern __shared__ __align__(1024) uint8_t smem[];
    const uint32_t sb = smem_u32(smem);

    const int tid  = threadIdx.x;
    const int lane = tid & 31;
    const int wid  = tid >> 5;                   // 0..15
    const int wm   = (wid >> 3) * 64;            // 0 or 64
    const int wn   = (wid & 7) * 32;             // 0..224
    const int b    = blockIdx.z;
    const int m0   = blockIdx.y * 128;
    const int n0   = blockIdx.x * 256;

    const fp16* Ah = ((MODE == 0) ? g_Qh : g_Ph)  + b * SA + (size_t)m0 * LDA;
    const fp16* Al = ((MODE == 0) ? g_Ql : g_Pl)  + b * SA + (size_t)m0 * LDA;
    const fp16* Bh = ((MODE == 0) ? g_Kh : g_Vth) + b * SB + (size_t)n0 * LDB;
    const fp16* Bl = ((MODE == 0) ? g_Kl : g_Vtl) + b * SB + (size_t)n0 * LDB;
    float* C = ((MODE == 0) ? g_E : Oout) + b * SC;

    float acc[4][4][4];
    #pragma unroll
    for (int i = 0; i < 4; i++)
        #pragma unroll
        for (int j = 0; j < 4; j++)
            #pragma unroll
            for (int q = 0; q < 4; q++) acc[i][j][q] = 0.0f;

    const int a_r15 = lane & 15;
    const int c_hi  = lane >> 4;

    // Prologue: fill stage 0
    cp_tile<128>(sb + OFF_AH, Ah, LDA, tid);
    cp_tile<128>(sb + OFF_AL, Al, LDA, tid);
    cp_tile<256>(sb + OFF_BH, Bh, LDB, tid);
    cp_tile<256>(sb + OFF_BL, Bl, LDB, tid);
    CP_COMMIT();

    for (int it = 0; it < NITER; ++it) {
        CP_WAIT0();
        __syncthreads();

        if (it + 1 < NITER) {
            const uint32_t nb = sb + ((it + 1) & 1) * STAGE_B;
            const int k0 = (it + 1) * 64;
            cp_tile<128>(nb + OFF_AH, Ah + k0, LDA, tid);
            cp_tile<128>(nb + OFF_AL, Al + k0, LDA, tid);
            cp_tile<256>(nb + OFF_BH, Bh + k0, LDB, tid);
            cp_tile<256>(nb + OFF_BL, Bl + k0, LDB, tid);
            CP_COMMIT();
        }

        const uint32_t SBASE = sb + (it & 1) * STAGE_B;

        #pragma unroll
        for (int kk = 0; kk < 4; ++kk) {
            uint32_t af[4][4], bfh[2][4], bfl[2][4];
            lds_a(SBASE + OFF_AH, kk, wm, a_r15, c_hi, af);   // Ah
            lds_b(SBASE + OFF_BH, kk, wn, a_r15, c_hi, bfh);  // Bh
            lds_b(SBASE + OFF_BL, kk, wn, a_r15, c_hi, bfl);  // Bl
            mma_step(acc, af, bfh);                            // Ah*Bh
            mma_step(acc, af, bfl);                            // Ah*Bl
            lds_a(SBASE + OFF_AL, kk, wm, a_r15, c_hi, af);   // Al (reuse regs)
            mma_step(acc, af, bfh);                            // Al*Bh
        }
    }
    CP_WAIT0();   // drain (no-op if NITER tail already waited)

    // Epilogue
    const int g  = lane >> 2;
    const int ti = lane & 3;
    #pragma unroll
    for (int mi = 0; mi < 4; ++mi) {
        #pragma unroll
        for (int ni = 0; ni < 4; ++ni) {
            const int row = m0 + wm + mi * 16 + g;
            const int col = n0 + wn + ni * 8 + ti * 2;
            *(float2*)&C[(size_t)row * LDC + col] =
                make_float2(acc[mi][ni][0], acc[mi][ni][1]);
            *(float2*)&C[(size_t)(row + 8) * LDC + col] =
                make_float2(acc[mi][ni][2], acc[mi][ni][3]);
        }
    }
}

// ---------------------------------------------------------------------------
extern "C" void kernel_launch(void* const* d_in, const int* in_sizes, int n_in,
                              void* d_out, int out_size)
{
    const float* Q = (const float*)d_in[0];
    const float* K = (const float*)d_in[1];
    const float* V = (const float*)d_in[2];
    float*       O = (float*)d_out;

    cudaFuncSetAttribute(hgemm3_kernel<0>, cudaFuncAttributeMaxDynamicSharedMemorySize, SMEM_T);
    cudaFuncSetAttribute(hgemm3_kernel<1>, cudaFuncAttributeMaxDynamicSharedMemorySize, SMEM_T);

    const int n4 = NB * QDIM * EDIM / 4;
    split_kernel<<<(n4 + 255) / 256, 256>>>(Q, 0, n4);
    split_kernel<<<(n4 + 255) / 256, 256>>>(K, 1, n4);
    vtrans_kernel<<<dim3(KDIM / 32, EDIM / 32, NB), 256>>>(V);

    hgemm3_kernel<0><<<dim3(KDIM / 256, QDIM / 128, NB), 512, SMEM_T>>>(nullptr);

    softmax_split_kernel<<<NB * QDIM, 256>>>();

    hgemm3_kernel<1><<<dim3(EDIM / 256, QDIM / 128, NB), 512, SMEM_T>>>(O);
}

// round 7
// speedup vs baseline: 3.1696x; 1.1923x over previous
#include <cuda_runtime.h>
#include <cuda_fp16.h>
#include <cstdint>

#define NB   8
#define QDIM 2048
#define KDIM 2048
#define EDIM 512

typedef __half fp16;

// ---------------------------------------------------------------------------
// Device-global scratch (allocation-guard-safe)
// ---------------------------------------------------------------------------
__device__ __align__(256) fp16  g_Qh[(size_t)NB * QDIM * EDIM];
__device__ __align__(256) fp16  g_Ql[(size_t)NB * QDIM * EDIM];
__device__ __align__(256) fp16  g_Kh[(size_t)NB * KDIM * EDIM];
__device__ __align__(256) fp16  g_Kl[(size_t)NB * KDIM * EDIM];
__device__ __align__(256) fp16  g_Vth[(size_t)NB * EDIM * KDIM];  // V^T [b][e][k]
__device__ __align__(256) fp16  g_Vtl[(size_t)NB * EDIM * KDIM];
__device__ __align__(256) float g_E  [(size_t)NB * QDIM * KDIM];  // logits
__device__ __align__(256) fp16  g_Ph [(size_t)NB * QDIM * KDIM];  // softmax (hi only)

// ---------------------------------------------------------------------------
// PTX helpers (plain sm_80+ features only — virtual arch is compute_103)
// ---------------------------------------------------------------------------
__device__ __forceinline__ uint32_t smem_u32(const void* p) {
    uint32_t a;
    asm("{ .reg .u64 t; cvta.to.shared.u64 t, %1; cvt.u32.u64 %0, t; }" : "=r"(a) : "l"(p));
    return a;
}

__device__ __forceinline__ uint32_t h2_u32(__half2 h) {
    union { __half2 h; uint32_t u; } c;
    c.h = h;
    return c.u;
}

#define CP_ASYNC16(dst, src) \
    asm volatile("cp.async.cg.shared.global [%0], [%1], 16;" :: "r"(dst), "l"(src))
#define CP_COMMIT() asm volatile("cp.async.commit_group;" ::: "memory")
#define CP_WAIT0()  asm volatile("cp.async.wait_group 0;" ::: "memory")

#define LDSM_X4(r0, r1, r2, r3, a)                                          \
    asm volatile("ldmatrix.sync.aligned.m8n8.x4.shared.b16 {%0,%1,%2,%3}, [%4];" \
        : "=r"(r0), "=r"(r1), "=r"(r2), "=r"(r3) : "r"(a))

#define MMA16816(d, a, b0, b1)                                              \
    asm volatile("mma.sync.aligned.m16n8k16.row.col.f32.f16.f16.f32 "       \
        "{%0,%1,%2,%3},{%4,%5,%6,%7},{%8,%9},{%0,%1,%2,%3};"                \
        : "+f"((d)[0]), "+f"((d)[1]), "+f"((d)[2]), "+f"((d)[3])            \
        : "r"((a)[0]), "r"((a)[1]), "r"((a)[2]), "r"((a)[3]),               \
          "r"(b0), "r"(b1))

// ---------------------------------------------------------------------------
// Elementwise fp32 -> fp16 hi/lo split  (which: 0 = Q, 1 = K)
// ---------------------------------------------------------------------------
__global__ __launch_bounds__(256)
void split_kernel(const float* __restrict__ X, int which, int n4)
{
    fp16* Xh = which ? g_Kh : g_Qh;
    fp16* Xl = which ? g_Kl : g_Ql;
    int i = blockIdx.x * 256 + threadIdx.x;
    if (i >= n4) return;
    float4 v = ((const float4*)X)[i];
    fp16 h0 = __float2half_rn(v.x), h1 = __float2half_rn(v.y);
    fp16 h2 = __float2half_rn(v.z), h3 = __float2half_rn(v.w);
    fp16 l0 = __float2half_rn(v.x - __half2float(h0));
    fp16 l1 = __float2half_rn(v.y - __half2float(h1));
    fp16 l2 = __float2half_rn(v.z - __half2float(h2));
    fp16 l3 = __float2half_rn(v.w - __half2float(h3));
    ((__half2*)Xh)[2 * i]     = __half2(h0, h1);
    ((__half2*)Xh)[2 * i + 1] = __half2(h2, h3);
    ((__half2*)Xl)[2 * i]     = __half2(l0, l1);
    ((__half2*)Xl)[2 * i + 1] = __half2(l2, l3);
}

// ---------------------------------------------------------------------------
// V [b][k][e] fp32 -> V^T [b][e][k] fp16 hi/lo
// ---------------------------------------------------------------------------
__global__ __launch_bounds__(256)
void vtrans_kernel(const float* __restrict__ V)
{
    __shared__ float t[32][33];
    const int b  = blockIdx.z;
    const int k0 = blockIdx.x * 32;
    const int e0 = blockIdx.y * 32;
    const int tx = threadIdx.x & 31;
    const int ty = threadIdx.x >> 5;
    const float* Vb = V + (size_t)b * KDIM * EDIM;

    #pragma unroll
    for (int j = 0; j < 4; j++)
        t[ty + j * 8][tx] = Vb[(size_t)(k0 + ty + j * 8) * EDIM + e0 + tx];
    __syncthreads();

    #pragma unroll
    for (int j = 0; j < 4; j++) {
        int e = e0 + ty + j * 8;
        int k = k0 + tx;
        float x = t[tx][ty + j * 8];
        fp16 h = __float2half_rn(x);
        fp16 l = __float2half_rn(x - __half2float(h));
        size_t o = (size_t)b * EDIM * KDIM + (size_t)e * KDIM + k;
        g_Vth[o] = h;
        g_Vtl[o] = l;
    }
}

// ---------------------------------------------------------------------------
// Row softmax of g_E -> fp16 (hi only) in g_Ph  (float4 I/O)
// ---------------------------------------------------------------------------
__global__ __launch_bounds__(256)
void softmax_split_kernel()
{
    const size_t row = blockIdx.x;
    const float* p = g_E + row * (size_t)KDIM;
    const int tid = threadIdx.x;

    float4 va = ((const float4*)p)[tid];
    float4 vb = ((const float4*)p)[tid + 256];

    float m = fmaxf(fmaxf(fmaxf(va.x, va.y), fmaxf(va.z, va.w)),
                    fmaxf(fmaxf(vb.x, vb.y), fmaxf(vb.z, vb.w)));

    __shared__ float red[8];
    #pragma unroll
    for (int off = 16; off > 0; off >>= 1) m = fmaxf(m, __shfl_xor_sync(~0u, m, off));
    if ((tid & 31) == 0) red[tid >> 5] = m;
    __syncthreads();
    if (tid < 8) {
        float t = red[tid];
        #pragma unroll
        for (int off = 4; off > 0; off >>= 1) t = fmaxf(t, __shfl_xor_sync(0xFFu, t, off));
        red[tid] = t;
    }
    __syncthreads();
    m = red[0];

    va.x = __expf(va.x - m); va.y = __expf(va.y - m);
    va.z = __expf(va.z - m); va.w = __expf(va.w - m);
    vb.x = __expf(vb.x - m); vb.y = __expf(vb.y - m);
    vb.z = __expf(vb.z - m); vb.w = __expf(vb.w - m);
    float s = (va.x + va.y) + (va.z + va.w) + (vb.x + vb.y) + (vb.z + vb.w);

    __shared__ float red2[8];
    #pragma unroll
    for (int off = 16; off > 0; off >>= 1) s += __shfl_xor_sync(~0u, s, off);
    if ((tid & 31) == 0) red2[tid >> 5] = s;
    __syncthreads();
    if (tid < 8) {
        float t = red2[tid];
        #pragma unroll
        for (int off = 4; off > 0; off >>= 1) t += __shfl_xor_sync(0xFFu, t, off);
        red2[tid] = t;
    }
    __syncthreads();
    const float inv = 1.0f / red2[0];

    fp16* ph = g_Ph + row * (size_t)KDIM;
    __half2 hh[4];
    hh[0] = __half2(__float2half_rn(va.x * inv), __float2half_rn(va.y * inv));
    hh[1] = __half2(__float2half_rn(va.z * inv), __float2half_rn(va.w * inv));
    hh[2] = __half2(__float2half_rn(vb.x * inv), __float2half_rn(vb.y * inv));
    hh[3] = __half2(__float2half_rn(vb.z * inv), __float2half_rn(vb.w * inv));
    *(uint2*)&ph[tid * 4]        = make_uint2(h2_u32(hh[0]), h2_u32(hh[1]));
    *(uint2*)&ph[1024 + tid * 4] = make_uint2(h2_u32(hh[2]), h2_u32(hh[3]));
}

// ---------------------------------------------------------------------------
// HMMA split-fp16 GEMM.
//   MODE 0 (3 passes): E = Q.K^T   A = Qh/Ql [2048x512], B = Kh/Kl [2048x512]
//   MODE 1 (2 passes): O = P.V     A = Ph    [2048x2048], B = Vth/Vtl [512x2048]
// CTA tile 128x256, 512 threads (16 warps, 2x8 grid), warp tile 64x32.
// K-chunk 64, 2-stage cp.async ring, kk-major pass order w/ fragment reuse.
// ---------------------------------------------------------------------------

// Copy a ROWS x 64 fp16 tile (row-major, stride ld halfs) into swizzled smem.
template <int ROWS>
__device__ __forceinline__ void cp_tile(uint32_t dstbase, const fp16* src,
                                        int ld, int tid)
{
    const int c = tid & 7;                       // 16B chunk within 128B row
    const char* s = (const char*)src + c * 16;
    const size_t row_bytes = (size_t)ld * 2;
    #pragma unroll
    for (int r0 = 0; r0 < ROWS; r0 += 64) {
        int r = r0 + (tid >> 3);                 // 512 threads -> 64 rows/step
        uint32_t dst = dstbase + (uint32_t)r * 128u + (uint32_t)((c ^ (r & 7)) << 4);
        CP_ASYNC16(dst, s + (size_t)r * row_bytes);
    }
}

__device__ __forceinline__ void lds_a(uint32_t base, int kk, int wm,
                                      int a_r15, int c_hi, uint32_t af[4][4])
{
    #pragma unroll
    for (int mi = 0; mi < 4; ++mi) {
        const int row = wm + mi * 16 + a_r15;
        const uint32_t addr = base + (uint32_t)row * 128u
            + (uint32_t)(((kk * 2 + c_hi) ^ (row & 7)) << 4);
        LDSM_X4(af[mi][0], af[mi][1], af[mi][2], af[mi][3], addr);
    }
}

__device__ __forceinline__ void lds_b(uint32_t base, int kk, int wn,
                                      int a_r15, int c_hi, uint32_t bf[2][4])
{
    #pragma unroll
    for (int nj = 0; nj < 2; ++nj) {
        const int row = wn + nj * 16 + a_r15;
        const uint32_t addr = base + (uint32_t)row * 128u
            + (uint32_t)(((kk * 2 + c_hi) ^ (row & 7)) << 4);
        LDSM_X4(bf[nj][0], bf[nj][1], bf[nj][2], bf[nj][3], addr);
    }
}

__device__ __forceinline__ void mma_step(float acc[4][4][4],
                                         uint32_t af[4][4], uint32_t bf[2][4])
{
    #pragma unroll
    for (int mi = 0; mi < 4; ++mi) {
        #pragma unroll
        for (int ni = 0; ni < 4; ++ni) {
            const uint32_t b0 = bf[ni >> 1][(ni & 1) ? 1 : 0];
            const uint32_t b1 = bf[ni >> 1][(ni & 1) ? 3 : 2];
            MMA16816(acc[mi][ni], af[mi], b0, b1);
        }
    }
}

template <int MODE>
__global__ __launch_bounds__(512, 1)
void hgemm3_kernel(float* __restrict__ Oout)
{
    constexpr int LDA  = (MODE == 0) ? EDIM : KDIM;
    constexpr int LDB  = (MODE == 0) ? EDIM : KDIM;
    constexpr int LDC  = (MODE == 0) ? KDIM : EDIM;
    constexpr int KTOT = (MODE == 0) ? EDIM : KDIM;
    constexpr size_t SA = (MODE == 0) ? (size_t)QDIM * EDIM : (size_t)QDIM * KDIM;
    constexpr size_t SB = (MODE == 0) ? (size_t)KDIM * EDIM : (size_t)EDIM * KDIM;
    constexpr size_t SC = (MODE == 0) ? (size_t)QDIM * KDIM : (size_t)QDIM * EDIM;
    constexpr int NITER = KTOT / 64;

    // Stage layout (bytes): A_hi [A_lo] B_hi B_lo
    constexpr uint32_t OFF_AH = 0;
    constexpr uint32_t OFF_AL = 16384;                          // MODE 0 only
    constexpr uint32_t OFF_BH = (MODE == 0) ? 32768 : 16384;
    constexpr uint32_t OFF_BL = OFF_BH + 32768;
    constexpr uint32_t STAGE  = OFF_BL + 32768;                  // 96K / 80K

    extern __shared__ __align__(1024) uint8_t smem[];
    const uint32_t sb = smem_u32(smem);

    const int tid  = threadIdx.x;
    const int lane = tid & 31;
    const int wid  = tid >> 5;                   // 0..15
    const int wm   = (wid >> 3) * 64;            // 0 or 64
    const int wn   = (wid & 7) * 32;             // 0..224
    const int b    = blockIdx.z;
    const int m0   = blockIdx.y * 128;
    const int n0   = blockIdx.x * 256;

    const fp16* Ah = ((MODE == 0) ? g_Qh : g_Ph)  + b * SA + (size_t)m0 * LDA;
    const fp16* Al = g_Ql + b * SA + (size_t)m0 * LDA;          // MODE 0 only
    const fp16* Bh = ((MODE == 0) ? g_Kh : g_Vth) + b * SB + (size_t)n0 * LDB;
    const fp16* Bl = ((MODE == 0) ? g_Kl : g_Vtl) + b * SB + (size_t)n0 * LDB;
    float* C = ((MODE == 0) ? g_E : Oout) + b * SC;

    float acc[4][4][4];
    #pragma unroll
    for (int i = 0; i < 4; i++)
        #pragma unroll
        for (int j = 0; j < 4; j++)
            #pragma unroll
            for (int q = 0; q < 4; q++) acc[i][j][q] = 0.0f;

    const int a_r15 = lane & 15;
    const int c_hi  = lane >> 4;

    // Prologue: fill stage 0
    cp_tile<128>(sb + OFF_AH, Ah, LDA, tid);
    if (MODE == 0) cp_tile<128>(sb + OFF_AL, Al, LDA, tid);
    cp_tile<256>(sb + OFF_BH, Bh, LDB, tid);
    cp_tile<256>(sb + OFF_BL, Bl, LDB, tid);
    CP_COMMIT();

    for (int it = 0; it < NITER; ++it) {
        CP_WAIT0();
        __syncthreads();

        if (it + 1 < NITER) {
            const uint32_t nb = sb + ((it + 1) & 1) * STAGE;
            const int k0 = (it + 1) * 64;
            cp_tile<128>(nb + OFF_AH, Ah + k0, LDA, tid);
            if (MODE == 0) cp_tile<128>(nb + OFF_AL, Al + k0, LDA, tid);
            cp_tile<256>(nb + OFF_BH, Bh + k0, LDB, tid);
            cp_tile<256>(nb + OFF_BL, Bl + k0, LDB, tid);
            CP_COMMIT();
        }

        const uint32_t SBASE = sb + (it & 1) * STAGE;

        #pragma unroll
        for (int kk = 0; kk < 4; ++kk) {
            uint32_t af[4][4], bfh[2][4], bfl[2][4];
            lds_a(SBASE + OFF_AH, kk, wm, a_r15, c_hi, af);   // A hi
            lds_b(SBASE + OFF_BH, kk, wn, a_r15, c_hi, bfh);  // B hi
            lds_b(SBASE + OFF_BL, kk, wn, a_r15, c_hi, bfl);  // B lo
            mma_step(acc, af, bfh);                            // Ah*Bh
            mma_step(acc, af, bfl);                            // Ah*Bl
            if (MODE == 0) {
                lds_a(SBASE + OFF_AL, kk, wm, a_r15, c_hi, af);  // A lo (reuse)
                mma_step(acc, af, bfh);                           // Al*Bh
            }
        }
    }
    CP_WAIT0();

    // Epilogue
    const int g  = lane >> 2;
    const int ti = lane & 3;
    #pragma unroll
    for (int mi = 0; mi < 4; ++mi) {
        #pragma unroll
        for (int ni = 0; ni < 4; ++ni) {
            const int row = m0 + wm + mi * 16 + g;
            const int col = n0 + wn + ni * 8 + ti * 2;
            *(float2*)&C[(size_t)row * LDC + col] =
                make_float2(acc[mi][ni][0], acc[mi][ni][1]);
            *(float2*)&C[(size_t)(row + 8) * LDC + col] =
                make_float2(acc[mi][ni][2], acc[mi][ni][3]);
        }
    }
}

// ---------------------------------------------------------------------------
extern "C" void kernel_launch(void* const* d_in, const int* in_sizes, int n_in,
                              void* d_out, int out_size)
{
    const float* Q = (const float*)d_in[0];
    const float* K = (const float*)d_in[1];
    const float* V = (const float*)d_in[2];
    float*       O = (float*)d_out;

    const int SMEM_T0 = 2 * (3 * 16384 + 2 * 32768 - 16384);   // 2 * 96K = 196608
    const int SMEM_T1 = 2 * (16384 + 2 * 32768);               // 2 * 80K = 163840

    cudaFuncSetAttribute(hgemm3_kernel<0>, cudaFuncAttributeMaxDynamicSharedMemorySize, 196608);
    cudaFuncSetAttribute(hgemm3_kernel<1>, cudaFuncAttributeMaxDynamicSharedMemorySize, 163840);

    const int n4 = NB * QDIM * EDIM / 4;
    split_kernel<<<(n4 + 255) / 256, 256>>>(Q, 0, n4);
    split_kernel<<<(n4 + 255) / 256, 256>>>(K, 1, n4);
    vtrans_kernel<<<dim3(KDIM / 32, EDIM / 32, NB), 256>>>(V);

    hgemm3_kernel<0><<<dim3(KDIM / 256, QDIM / 128, NB), 512, 196608>>>(nullptr);

    softmax_split_kernel<<<NB * QDIM, 256>>>();

    hgemm3_kernel<1><<<dim3(EDIM / 256, QDIM / 128, NB), 512, 163840>>>(O);

    (void)SMEM_T0; (void)SMEM_T1;
}